// round 12
// baseline (speedup 1.0000x reference)
#include <cuda_runtime.h>
#include <math.h>

#define NPIX 4096   // H*W
#define NBH  4096   // B*HP

// Scratch (no allocation allowed -> __device__ globals)
__device__ float g_stats[NBH * 12];
__device__ float g_feat[NBH * 32];

__device__ __forceinline__ float wredsum(float v) {
#pragma unroll
    for (int o = 16; o; o >>= 1) v += __shfl_xor_sync(0xffffffffu, v, o);
    return v;
}

// FMA-only sigmoid: no MUFU. abs err < ~1e-6.
__device__ __forceinline__ float fsig(float x) {
    x = fmaxf(-18.f, fminf(18.f, x));
    float z = x * -1.4426950408889634f;
    float fz = z + 12582912.0f;
    int iz = __float_as_int(fz) - 0x4B400000;
    float zf = z - (float)iz;
    float p = 0.00133335581f;
    p = fmaf(p, zf, 0.00961812911f);
    p = fmaf(p, zf, 0.05550410866f);
    p = fmaf(p, zf, 0.24022650700f);
    p = fmaf(p, zf, 0.69314718056f);
    p = fmaf(p, zf, 1.0f);
    float scale = __int_as_float((iz + 127) << 23);
    float y = fmaf(p, scale, 1.0f);              // 1 + e^-x
    float r = __int_as_float(0x7EF311C3 - __float_as_int(y));
    r = r * (2.0f - y * r);
    r = r * (2.0f - y * r);
    r = r * (2.0f - y * r);
    return r;
}

// ============================================================================
// Kernel 1: stats. 512 threads/block, ONE slice/block (grid 4096).
// Small register footprint -> ~100% occupancy -> max chip MLP.
// ============================================================================
__global__ __launch_bounds__(512) void k_stats(const float* __restrict__ a,
                                               const float* __restrict__ b) {
    const int slice = blockIdx.x;
    const float4* a4 = (const float4*)a + slice * 1024;
    const float4* b4 = (const float4*)b + slice * 1024;
    const int t = threadIdx.x;
    const int wid = t >> 5, lane = t & 31;

    __shared__ float sh[16][11];

    float4 va0 = a4[t], va1 = a4[t + 512];
    float4 vb0 = b4[t], vb1 = b4[t + 512];

    float sx = 0.f, sxx = 0.f, sy = 0.f, syy = 0.f, sxy = 0.f, sd = 0.f, sdd = 0.f;
    float mnx = INFINITY, mxx = -INFINITY, mny = INFINITY, mxy = -INFINITY;

#define ACCUM4(VA, VB)                                                    \
    {                                                                     \
        float xs[4] = {VA.x, VA.y, VA.z, VA.w};                           \
        float ys[4] = {VB.x, VB.y, VB.z, VB.w};                           \
        _Pragma("unroll")                                                 \
        for (int e = 0; e < 4; e++) {                                     \
            float x = xs[e], y = ys[e];                                   \
            sx += x; sxx += x * x; sy += y; syy += y * y; sxy += x * y;   \
            float d = x - y; sd += d; sdd += d * d;                       \
            mnx = fminf(mnx, x); mxx = fmaxf(mxx, x);                     \
            mny = fminf(mny, y); mxy = fmaxf(mxy, y);                     \
        }                                                                 \
    }
    ACCUM4(va0, vb0);
    ACCUM4(va1, vb1);
#undef ACCUM4

    // warp reduction
#pragma unroll
    for (int o = 16; o; o >>= 1) {
        sx += __shfl_xor_sync(0xffffffffu, sx, o);
        sxx += __shfl_xor_sync(0xffffffffu, sxx, o);
        sy += __shfl_xor_sync(0xffffffffu, sy, o);
        syy += __shfl_xor_sync(0xffffffffu, syy, o);
        sxy += __shfl_xor_sync(0xffffffffu, sxy, o);
        sd += __shfl_xor_sync(0xffffffffu, sd, o);
        sdd += __shfl_xor_sync(0xffffffffu, sdd, o);
        mnx = fminf(mnx, __shfl_xor_sync(0xffffffffu, mnx, o));
        mxx = fmaxf(mxx, __shfl_xor_sync(0xffffffffu, mxx, o));
        mny = fminf(mny, __shfl_xor_sync(0xffffffffu, mny, o));
        mxy = fmaxf(mxy, __shfl_xor_sync(0xffffffffu, mxy, o));
    }
    if (lane == 0) {
        float* r = sh[wid];
        r[0] = sx; r[1] = sxx; r[2] = sy; r[3] = syy; r[4] = sxy;
        r[5] = sd; r[6] = sdd; r[7] = mnx; r[8] = mxx; r[9] = mny; r[10] = mxy;
    }
    __syncthreads();

    if (t < 16) {
        float v0 = sh[t][0], v1 = sh[t][1], v2 = sh[t][2], v3 = sh[t][3], v4 = sh[t][4];
        float v5 = sh[t][5], v6 = sh[t][6];
        float m7 = sh[t][7], m8 = sh[t][8], m9 = sh[t][9], m10 = sh[t][10];
#pragma unroll
        for (int o = 8; o; o >>= 1) {
            v0 += __shfl_xor_sync(0xffffu, v0, o);
            v1 += __shfl_xor_sync(0xffffu, v1, o);
            v2 += __shfl_xor_sync(0xffffu, v2, o);
            v3 += __shfl_xor_sync(0xffffu, v3, o);
            v4 += __shfl_xor_sync(0xffffu, v4, o);
            v5 += __shfl_xor_sync(0xffffu, v5, o);
            v6 += __shfl_xor_sync(0xffffu, v6, o);
            m7 = fminf(m7, __shfl_xor_sync(0xffffu, m7, o));
            m8 = fmaxf(m8, __shfl_xor_sync(0xffffu, m8, o));
            m9 = fminf(m9, __shfl_xor_sync(0xffffu, m9, o));
            m10 = fmaxf(m10, __shfl_xor_sync(0xffffu, m10, o));
        }
        if (t == 0) {
            const float N = 4096.f, NM1 = 4095.f;
            float mean_a = v0 / N;
            float std_a = sqrtf(fmaxf(0.f, (v1 - v0 * v0 / N) / NM1));
            float mean_b = v2 / N;
            float std_b = sqrtf(fmaxf(0.f, (v3 - v2 * v2 / N) / NM1));
            float mean_d = v5 / N;
            float std_d = sqrtf(fmaxf(0.f, (v6 - v5 * v5 / N) / NM1));
            float norm_d = sqrtf(fmaxf(0.f, v6));
            float na = sqrtf(fmaxf(0.f, v1)), nb = sqrtf(fmaxf(0.f, v3));
            float cosv = v4 / (fmaxf(na, 1e-8f) * fmaxf(nb, 1e-8f));
            float* o = g_stats + slice * 12;
            o[0] = mean_a; o[1] = std_a; o[2] = m7; o[3] = m8;
            o[4] = mean_b; o[5] = std_b; o[6] = m9; o[7] = m10;
            o[8] = mean_d; o[9] = std_d; o[10] = norm_d; o[11] = cosv;
        }
    }
}

// ============================================================================
// Kernel 2: transformer core (exact R9 code — part of 81.9us baseline)
// ============================================================================
#define OFF_WINP  0
#define OFF_WQ    416
#define OFF_WKV   1568
#define OFF_WOUT  3872
#define OFF_WF1   5024
#define OFF_WF2   7328
#define OFF_STATS 9504
#define OFF_FEAT  10272
#define OFF_X     12320
#define OFF_KV    14624
#define OFF_PROBS 18976
#define SM_FLOATS 20000
#define XS 36

__global__ __launch_bounds__(512) void k_transformer(
    const float* __restrict__ layer_emb,
    const float* __restrict__ in_proj_w, const float* __restrict__ in_proj_b,
    const float* __restrict__ ln1_g, const float* __restrict__ ln1_b,
    const float* __restrict__ qkv_w, const float* __restrict__ qkv_b,
    const float* __restrict__ out_w, const float* __restrict__ out_b,
    const float* __restrict__ ln2_g, const float* __restrict__ ln2_b,
    const float* __restrict__ ffn_w1, const float* __restrict__ ffn_b1,
    const float* __restrict__ ffn_w2, const float* __restrict__ ffn_b2) {
    extern __shared__ float sm[];

    const int bidx = blockIdx.x >> 1;
    const int half = blockIdx.x & 1;
    const int t = threadIdx.x, lane = t & 31, wp = t >> 5;
    const int hp8 = t >> 3, jg = t & 7;
    const int lr = t >> 4, jgR = t & 15;
    const int rowR = half * 32 + lr;

    for (int o = t; o < 768; o += 512) sm[OFF_STATS + o] = g_stats[bidx * 768 + o];
    for (int o = t; o < 384; o += 512) sm[OFF_WINP + (o / 12) * 13 + (o % 12)] = in_proj_w[o];
    for (int o = t; o < 1024; o += 512) sm[OFF_WQ + (o >> 5) * 36 + (o & 31)] = qkv_w[o];
    for (int o = t; o < 2048; o += 512) sm[OFF_WKV + (o >> 5) * 36 + (o & 31)] = qkv_w[1024 + o];
    for (int o = t; o < 1024; o += 512) sm[OFF_WOUT + (o >> 5) * 36 + (o & 31)] = out_w[o];
    for (int o = t; o < 2048; o += 512) sm[OFF_WF1 + (o >> 5) * 36 + (o & 31)] = ffn_w1[o];
    for (int o = t; o < 2048; o += 512) sm[OFF_WF2 + (o >> 6) * 68 + (o & 63)] = ffn_w2[o];
    __syncthreads();

    for (int o = t; o < 2048; o += 512) {
        int hp = o >> 5, d = o & 31;
        float acc = in_proj_b[d] + layer_emb[d];
#pragma unroll
        for (int s = 0; s < 12; s++) acc += sm[OFF_STATS + hp * 12 + s] * sm[OFF_WINP + d * 13 + s];
        sm[OFF_FEAT + o] = acc;
    }
    __syncthreads();

#pragma unroll
    for (int rep = 0; rep < 4; rep++) {
        int hp = rep * 16 + wp;
        float v = sm[OFF_FEAT + hp * 32 + lane];
        float mu = wredsum(v) * (1.f / 32.f);
        float df = v - mu;
        float var = wredsum(df * df) * (1.f / 32.f);
        sm[OFF_X + hp * XS + lane] = df * rsqrtf(var + 1e-5f) * ln1_g[lane] + ln1_b[lane];
    }
    __syncthreads();

    float xr[32];
#define LOAD_XR(BASE)                                           \
    {                                                           \
        _Pragma("unroll")                                       \
        for (int k8 = 0; k8 < 8; k8++) {                        \
            float4 v = *(const float4*)&sm[(BASE) + k8 * 4];    \
            xr[k8 * 4 + 0] = v.x; xr[k8 * 4 + 1] = v.y;         \
            xr[k8 * 4 + 2] = v.z; xr[k8 * 4 + 3] = v.w;         \
        }                                                       \
    }
#define DOT32(ACC, WBASE)                                       \
    {                                                           \
        _Pragma("unroll")                                       \
        for (int k8 = 0; k8 < 8; k8++) {                        \
            float4 w4 = *(const float4*)&sm[(WBASE) + k8 * 4];  \
            ACC = fmaf(w4.x, xr[k8 * 4 + 0], ACC);              \
            ACC = fmaf(w4.y, xr[k8 * 4 + 1], ACC);              \
            ACC = fmaf(w4.z, xr[k8 * 4 + 2], ACC);              \
            ACC = fmaf(w4.w, xr[k8 * 4 + 3], ACC);              \
        }                                                       \
    }

    LOAD_XR(OFF_X + hp8 * XS);
#pragma unroll
    for (int jj = 0; jj < 8; jj++) {
        int j = jg + 8 * jj;
        float acc = qkv_b[32 + j];
        DOT32(acc, OFF_WKV + j * 36);
        sm[OFF_KV + hp8 * 65 + j] = acc;
    }
    const bool own = ((hp8 >> 5) == half);
    float qv[4];
    if (own) {
#pragma unroll
        for (int jj = 0; jj < 4; jj++) {
            int j = jg + 8 * jj;
            float acc = qkv_b[j];
            DOT32(acc, OFF_WQ + j * 36);
            qv[jj] = acc;
        }
    }
    __syncwarp();
    if (own) {
#pragma unroll
        for (int jj = 0; jj < 4; jj++) sm[OFF_X + hp8 * XS + jg + 8 * jj] = qv[jj];
    }
    __syncthreads();

    {
        const int dh = lane & 15, kvhalf = lane >> 4, hoff = kvhalf << 4;
        for (int c = 0; c < 4; c++) {
            int p = c * 16 + wp;
            int h = p >> 5, q = half * 32 + (p & 31);
            const float* qrow = &sm[OFF_X + q * XS + h * 16];
            float s0 = 0.f, s1 = 0.f;
#pragma unroll
            for (int d2 = 0; d2 < 16; d2++) {
                float qq = qrow[d2];
                s0 = fmaf(qq, sm[OFF_KV + lane * 65 + h * 16 + d2], s0);
                s1 = fmaf(qq, sm[OFF_KV + (lane + 32) * 65 + h * 16 + d2], s1);
            }
            float e0 = expf(s0 * 0.25f), e1 = expf(s1 * 0.25f);
            float inv = 1.f / wredsum(e0 + e1);
            sm[OFF_PROBS + wp * 64 + lane] = e0;
            sm[OFF_PROBS + wp * 64 + 32 + lane] = e1;
            __syncwarp();
            const float* pr = &sm[OFF_PROBS + wp * 64 + (kvhalf ? 32 : 0)];
            const float* vcol = &sm[OFF_KV + (kvhalf ? 32 * 65 : 0) + 32 + h * 16 + dh];
            float acc = 0.f;
#pragma unroll
            for (int k = 0; k < 32; k++) {
                int src = (k + hoff) & 31;
                acc = fmaf(pr[src], vcol[src * 65], acc);
            }
            acc += __shfl_xor_sync(0xffffffffu, acc, 16);
            if (lane < 16) sm[OFF_X + q * XS + h * 16 + lane] = acc * inv;
            __syncwarp();
        }
    }
    __syncthreads();

    LOAD_XR(OFF_X + rowR * XS);
#pragma unroll
    for (int jj = 0; jj < 2; jj++) {
        int j = jgR + 16 * jj;
        float acc = out_b[j];
        DOT32(acc, OFF_WOUT + j * 36);
        sm[OFF_FEAT + rowR * 32 + j] += acc;
    }
    __syncthreads();

#pragma unroll
    for (int rep = 0; rep < 2; rep++) {
        int hp = half * 32 + rep * 16 + wp;
        float v = sm[OFF_FEAT + hp * 32 + lane];
        float mu = wredsum(v) * (1.f / 32.f);
        float df = v - mu;
        float var = wredsum(df * df) * (1.f / 32.f);
        sm[OFF_X + hp * XS + lane] = df * rsqrtf(var + 1e-5f) * ln2_g[lane] + ln2_b[lane];
    }
    __syncthreads();

    LOAD_XR(OFF_X + rowR * XS);
#pragma unroll
    for (int jj = 0; jj < 4; jj++) {
        int f = jgR + 16 * jj;
        float acc = ffn_b1[f];
        DOT32(acc, OFF_WF1 + f * 36);
        sm[OFF_KV + lr * 68 + f] = 0.5f * acc * (1.f + erff(acc * 0.70710678118654752f));
    }
    __syncwarp();

#pragma unroll
    for (int jj = 0; jj < 2; jj++) {
        int d = jgR + 16 * jj;
        float acc = ffn_b2[d];
#pragma unroll
        for (int k8 = 0; k8 < 16; k8++) {
            float4 h4 = *(const float4*)&sm[OFF_KV + lr * 68 + k8 * 4];
            float4 w4 = *(const float4*)&sm[OFF_WF2 + d * 68 + k8 * 4];
            acc = fmaf(w4.x, h4.x, acc);
            acc = fmaf(w4.y, h4.y, acc);
            acc = fmaf(w4.z, h4.z, acc);
            acc = fmaf(w4.w, h4.w, acc);
        }
        g_feat[bidx * 2048 + rowR * 32 + d] = sm[OFF_FEAT + rowR * 32 + d] + acc;
    }
#undef LOAD_XR
#undef DOT32
}

// ============================================================================
// Kernel 3: heads + merge (exact R9 code — grid 4096, reversed, stcs)
// ============================================================================
__global__ __launch_bounds__(256) void k_merge(
    const float* __restrict__ a, const float* __restrict__ b,
    float* __restrict__ out,
    const float* __restrict__ gate_w, const float* __restrict__ gate_b,
    const float* __restrict__ row_w, const float* __restrict__ row_b,
    const float* __restrict__ col_w, const float* __restrict__ col_b,
    const float* __restrict__ drow_w, const float* __restrict__ drow_b,
    const float* __restrict__ dcol_w, const float* __restrict__ dcol_b,
    const float* __restrict__ delta_scale) {
    const int slice = (NBH - 1) - blockIdx.x;   // reverse: reuse k1's L2 tail
    const int t = threadIdx.x, lane = t & 31, wp = t >> 5;

    __shared__ float s_feat[32];
    __shared__ float s_r[64], s_c[64], s_dr[64], s_dc[64];
    __shared__ float s_gate;

    if (t < 32) s_feat[t] = g_feat[slice * 32 + t];
    __syncthreads();

    {
        const int mat = wp >> 1;
        const float* w; const float* bb; float* dst;
        if (mat == 0)      { w = row_w;  bb = row_b;  dst = s_r; }
        else if (mat == 1) { w = col_w;  bb = col_b;  dst = s_c; }
        else if (mat == 2) { w = drow_w; bb = drow_b; dst = s_dr; }
        else               { w = dcol_w; bb = dcol_b; dst = s_dc; }
        const int g = lane >> 3;
        const int dsub = lane & 7;
        float4 f4 = ((const float4*)s_feat)[dsub];
        const float dscale = (mat == 2) ? *delta_scale : 1.f;
#pragma unroll
        for (int ii = 0; ii < 8; ii++) {
            int i = (wp & 1) * 32 + ii * 4 + g;
            float4 w4 = ((const float4*)w)[i * 8 + dsub];
            float v = w4.x * f4.x + w4.y * f4.y + w4.z * f4.z + w4.w * f4.w;
            v += __shfl_xor_sync(0xffffffffu, v, 1);
            v += __shfl_xor_sync(0xffffffffu, v, 2);
            v += __shfl_xor_sync(0xffffffffu, v, 4);
            if (dsub == 0) dst[i] = (v + bb[i]) * dscale;
        }
        if (wp == 0) {
            float gv = s_feat[lane] * gate_w[lane];
            gv = wredsum(gv);
            if (lane == 0) s_gate = gv + gate_b[0];
        }
    }
    __syncthreads();

    const float4* a4 = (const float4*)a + slice * 1024;
    const float4* b4 = (const float4*)b + slice * 1024;
    float4* o4 = (float4*)out + slice * 1024;
    const float gate = s_gate;

    float4 va[4], vb[4];
#pragma unroll
    for (int k = 0; k < 4; k++) { va[k] = a4[t + k * 256]; vb[k] = b4[t + k * 256]; }
#pragma unroll
    for (int k = 0; k < 4; k++) {
        int p = t + k * 256;
        int i = p >> 4;
        float g = gate + s_r[i];
        float dr = s_dr[i];
        float4 c4 = ((const float4*)s_c)[p & 15];
        float4 dc4 = ((const float4*)s_dc)[p & 15];
        float4 r;
        { float m = fsig(g + c4.x); r.x = vb[k].x + m * (va[k].x - vb[k].x) + dr * dc4.x; }
        { float m = fsig(g + c4.y); r.y = vb[k].y + m * (va[k].y - vb[k].y) + dr * dc4.y; }
        { float m = fsig(g + c4.z); r.z = vb[k].z + m * (va[k].z - vb[k].z) + dr * dc4.z; }
        { float m = fsig(g + c4.w); r.w = vb[k].w + m * (va[k].w - vb[k].w) + dr * dc4.w; }
        __stcs(&o4[p], r);   // streaming store: don't pollute L2
    }
}

// ============================================================================
extern "C" void kernel_launch(void* const* d_in, const int* in_sizes, int n_in,
                              void* d_out, int out_size) {
    const float* a = (const float*)d_in[0];
    const float* b = (const float*)d_in[1];

    const int smem_bytes = SM_FLOATS * 4;
    cudaFuncSetAttribute(k_transformer, cudaFuncAttributeMaxDynamicSharedMemorySize,
                         smem_bytes);

    k_stats<<<NBH, 512>>>(a, b);

    k_transformer<<<128, 512, smem_bytes>>>(
        (const float*)d_in[2],
        (const float*)d_in[3], (const float*)d_in[4],
        (const float*)d_in[5], (const float*)d_in[6],
        (const float*)d_in[7], (const float*)d_in[8],
        (const float*)d_in[9], (const float*)d_in[10],
        (const float*)d_in[11], (const float*)d_in[12],
        (const float*)d_in[13], (const float*)d_in[14],
        (const float*)d_in[15], (const float*)d_in[16]);

    k_merge<<<NBH, 256>>>(
        a, b, (float*)d_out,
        (const float*)d_in[17], (const float*)d_in[18],
        (const float*)d_in[19], (const float*)d_in[20],
        (const float*)d_in[21], (const float*)d_in[22],
        (const float*)d_in[23], (const float*)d_in[24],
        (const float*)d_in[25], (const float*)d_in[26],
        (const float*)d_in[27]);
}

// round 13
// speedup vs baseline: 1.0804x; 1.0804x over previous
#include <cuda_runtime.h>
#include <math.h>

#define NPIX 4096   // H*W
#define NBH  4096   // B*HP

// Scratch (no allocation allowed -> __device__ globals)
__device__ float g_stats[NBH * 12];
__device__ float g_feat[NBH * 32];

// PDL primitives (no-ops when launch lacks the PDL attribute)
__device__ __forceinline__ void pdl_trigger() {
    asm volatile("griddepcontrol.launch_dependents;" ::: "memory");
}
__device__ __forceinline__ void pdl_wait() {
    asm volatile("griddepcontrol.wait;" ::: "memory");
}

__device__ __forceinline__ float wredsum(float v) {
#pragma unroll
    for (int o = 16; o; o >>= 1) v += __shfl_xor_sync(0xffffffffu, v, o);
    return v;
}
__device__ __forceinline__ float wredmax(float v) {
#pragma unroll
    for (int o = 16; o; o >>= 1) v = fmaxf(v, __shfl_xor_sync(0xffffffffu, v, o));
    return v;
}

// FMA-only sigmoid: no MUFU. abs err < ~1e-6.
__device__ __forceinline__ float fsig(float x) {
    x = fmaxf(-18.f, fminf(18.f, x));
    float z = x * -1.4426950408889634f;
    float fz = z + 12582912.0f;
    int iz = __float_as_int(fz) - 0x4B400000;
    float zf = z - (float)iz;
    float p = 0.00133335581f;
    p = fmaf(p, zf, 0.00961812911f);
    p = fmaf(p, zf, 0.05550410866f);
    p = fmaf(p, zf, 0.24022650700f);
    p = fmaf(p, zf, 0.69314718056f);
    p = fmaf(p, zf, 1.0f);
    float scale = __int_as_float((iz + 127) << 23);
    float y = fmaf(p, scale, 1.0f);              // 1 + e^-x
    float r = __int_as_float(0x7EF311C3 - __float_as_int(y));
    r = r * (2.0f - y * r);
    r = r * (2.0f - y * r);
    r = r * (2.0f - y * r);
    return r;
}

// ============================================================================
// Kernel 1: per-(b,hp) statistics — exact R9 shape (256 thr, measured 26.8us)
// ============================================================================
__global__ __launch_bounds__(256) void k_stats(const float* __restrict__ a,
                                               const float* __restrict__ b) {
    pdl_trigger();   // let k2 start staging weights under our tail
    const int slice = blockIdx.x;
    const float4* a4 = (const float4*)a + slice * (NPIX / 4);
    const float4* b4 = (const float4*)b + slice * (NPIX / 4);
    const int t = threadIdx.x;

    float sx = 0.f, sxx = 0.f, sy = 0.f, syy = 0.f, sxy = 0.f, sd = 0.f, sdd = 0.f;
    float mnx = INFINITY, mxx = -INFINITY, mny = INFINITY, mxy = -INFINITY;

    float4 va[4], vb[4];
#pragma unroll
    for (int k = 0; k < 4; k++) { va[k] = a4[t + k * 256]; vb[k] = b4[t + k * 256]; }
#pragma unroll
    for (int k = 0; k < 4; k++) {
        float xs[4] = {va[k].x, va[k].y, va[k].z, va[k].w};
        float ys[4] = {vb[k].x, vb[k].y, vb[k].z, vb[k].w};
#pragma unroll
        for (int e = 0; e < 4; e++) {
            float x = xs[e], y = ys[e];
            sx += x; sxx += x * x; sy += y; syy += y * y; sxy += x * y;
            float d = x - y; sd += d; sdd += d * d;
            mnx = fminf(mnx, x); mxx = fmaxf(mxx, x);
            mny = fminf(mny, y); mxy = fmaxf(mxy, y);
        }
    }

    sx = wredsum(sx); sxx = wredsum(sxx); sy = wredsum(sy); syy = wredsum(syy);
    sxy = wredsum(sxy); sd = wredsum(sd); sdd = wredsum(sdd);
    mnx = -wredmax(-mnx); mxx = wredmax(mxx);
    mny = -wredmax(-mny); mxy = wredmax(mxy);

    __shared__ float sh[8][11];
    const int wid = t >> 5, lane = t & 31;
    if (lane == 0) {
        float* r = sh[wid];
        r[0] = sx; r[1] = sxx; r[2] = sy; r[3] = syy; r[4] = sxy;
        r[5] = sd; r[6] = sdd; r[7] = mnx; r[8] = mxx; r[9] = mny; r[10] = mxy;
    }
    __syncthreads();
    if (t < 8) {
        float v0 = sh[t][0], v1 = sh[t][1], v2 = sh[t][2], v3 = sh[t][3], v4 = sh[t][4];
        float v5 = sh[t][5], v6 = sh[t][6];
        float m7 = sh[t][7], m8 = sh[t][8], m9 = sh[t][9], m10 = sh[t][10];
#pragma unroll
        for (int o = 4; o; o >>= 1) {
            v0 += __shfl_xor_sync(0xffu, v0, o);
            v1 += __shfl_xor_sync(0xffu, v1, o);
            v2 += __shfl_xor_sync(0xffu, v2, o);
            v3 += __shfl_xor_sync(0xffu, v3, o);
            v4 += __shfl_xor_sync(0xffu, v4, o);
            v5 += __shfl_xor_sync(0xffu, v5, o);
            v6 += __shfl_xor_sync(0xffu, v6, o);
            m7 = fminf(m7, __shfl_xor_sync(0xffu, m7, o));
            m8 = fmaxf(m8, __shfl_xor_sync(0xffu, m8, o));
            m9 = fminf(m9, __shfl_xor_sync(0xffu, m9, o));
            m10 = fmaxf(m10, __shfl_xor_sync(0xffu, m10, o));
        }
        if (t == 0) {
            const float N = 4096.f, NM1 = 4095.f;
            float mean_a = v0 / N;
            float std_a = sqrtf(fmaxf(0.f, (v1 - v0 * v0 / N) / NM1));
            float mean_b = v2 / N;
            float std_b = sqrtf(fmaxf(0.f, (v3 - v2 * v2 / N) / NM1));
            float mean_d = v5 / N;
            float std_d = sqrtf(fmaxf(0.f, (v6 - v5 * v5 / N) / NM1));
            float norm_d = sqrtf(fmaxf(0.f, v6));
            float na = sqrtf(fmaxf(0.f, v1)), nb = sqrtf(fmaxf(0.f, v3));
            float cosv = v4 / (fmaxf(na, 1e-8f) * fmaxf(nb, 1e-8f));
            float* o = g_stats + slice * 12;
            o[0] = mean_a; o[1] = std_a; o[2] = m7; o[3] = m8;
            o[4] = mean_b; o[5] = std_b; o[6] = m9; o[7] = m10;
            o[8] = mean_d; o[9] = std_d; o[10] = norm_d; o[11] = cosv;
        }
    }
}

// ============================================================================
// Kernel 2: transformer core (R9 logic) + PDL: stage weights BEFORE waiting
// on k1, trigger k3 at start.
// ============================================================================
#define OFF_WINP  0
#define OFF_WQ    416
#define OFF_WKV   1568
#define OFF_WOUT  3872
#define OFF_WF1   5024
#define OFF_WF2   7328
#define OFF_STATS 9504
#define OFF_FEAT  10272
#define OFF_X     12320
#define OFF_KV    14624
#define OFF_PROBS 18976
#define SM_FLOATS 20000
#define XS 36

__global__ __launch_bounds__(512) void k_transformer(
    const float* __restrict__ layer_emb,
    const float* __restrict__ in_proj_w, const float* __restrict__ in_proj_b,
    const float* __restrict__ ln1_g, const float* __restrict__ ln1_b,
    const float* __restrict__ qkv_w, const float* __restrict__ qkv_b,
    const float* __restrict__ out_w, const float* __restrict__ out_b,
    const float* __restrict__ ln2_g, const float* __restrict__ ln2_b,
    const float* __restrict__ ffn_w1, const float* __restrict__ ffn_b1,
    const float* __restrict__ ffn_w2, const float* __restrict__ ffn_b2) {
    extern __shared__ float sm[];

    pdl_trigger();   // let k3 start prefetching a/b under our execution

    const int bidx = blockIdx.x >> 1;
    const int half = blockIdx.x & 1;
    const int t = threadIdx.x, lane = t & 31, wp = t >> 5;
    const int hp8 = t >> 3, jg = t & 7;
    const int lr = t >> 4, jgR = t & 15;
    const int rowR = half * 32 + lr;

    // weight staging: independent of k1 -> overlap k1's tail
    for (int o = t; o < 384; o += 512) sm[OFF_WINP + (o / 12) * 13 + (o % 12)] = in_proj_w[o];
    for (int o = t; o < 1024; o += 512) sm[OFF_WQ + (o >> 5) * 36 + (o & 31)] = qkv_w[o];
    for (int o = t; o < 2048; o += 512) sm[OFF_WKV + (o >> 5) * 36 + (o & 31)] = qkv_w[1024 + o];
    for (int o = t; o < 1024; o += 512) sm[OFF_WOUT + (o >> 5) * 36 + (o & 31)] = out_w[o];
    for (int o = t; o < 2048; o += 512) sm[OFF_WF1 + (o >> 5) * 36 + (o & 31)] = ffn_w1[o];
    for (int o = t; o < 2048; o += 512) sm[OFF_WF2 + (o >> 6) * 68 + (o & 63)] = ffn_w2[o];

    pdl_wait();      // k1's g_stats writes now visible
    for (int o = t; o < 768; o += 512) sm[OFF_STATS + o] = g_stats[bidx * 768 + o];
    __syncthreads();

    for (int o = t; o < 2048; o += 512) {
        int hp = o >> 5, d = o & 31;
        float acc = in_proj_b[d] + layer_emb[d];
#pragma unroll
        for (int s = 0; s < 12; s++) acc += sm[OFF_STATS + hp * 12 + s] * sm[OFF_WINP + d * 13 + s];
        sm[OFF_FEAT + o] = acc;
    }
    __syncthreads();

#pragma unroll
    for (int rep = 0; rep < 4; rep++) {
        int hp = rep * 16 + wp;
        float v = sm[OFF_FEAT + hp * 32 + lane];
        float mu = wredsum(v) * (1.f / 32.f);
        float df = v - mu;
        float var = wredsum(df * df) * (1.f / 32.f);
        sm[OFF_X + hp * XS + lane] = df * rsqrtf(var + 1e-5f) * ln1_g[lane] + ln1_b[lane];
    }
    __syncthreads();

    float xr[32];
#define LOAD_XR(BASE)                                           \
    {                                                           \
        _Pragma("unroll")                                       \
        for (int k8 = 0; k8 < 8; k8++) {                        \
            float4 v = *(const float4*)&sm[(BASE) + k8 * 4];    \
            xr[k8 * 4 + 0] = v.x; xr[k8 * 4 + 1] = v.y;         \
            xr[k8 * 4 + 2] = v.z; xr[k8 * 4 + 3] = v.w;         \
        }                                                       \
    }
#define DOT32(ACC, WBASE)                                       \
    {                                                           \
        _Pragma("unroll")                                       \
        for (int k8 = 0; k8 < 8; k8++) {                        \
            float4 w4 = *(const float4*)&sm[(WBASE) + k8 * 4];  \
            ACC = fmaf(w4.x, xr[k8 * 4 + 0], ACC);              \
            ACC = fmaf(w4.y, xr[k8 * 4 + 1], ACC);              \
            ACC = fmaf(w4.z, xr[k8 * 4 + 2], ACC);              \
            ACC = fmaf(w4.w, xr[k8 * 4 + 3], ACC);              \
        }                                                       \
    }

    LOAD_XR(OFF_X + hp8 * XS);
#pragma unroll
    for (int jj = 0; jj < 8; jj++) {
        int j = jg + 8 * jj;
        float acc = qkv_b[32 + j];
        DOT32(acc, OFF_WKV + j * 36);
        sm[OFF_KV + hp8 * 65 + j] = acc;
    }
    const bool own = ((hp8 >> 5) == half);
    float qv[4];
    if (own) {
#pragma unroll
        for (int jj = 0; jj < 4; jj++) {
            int j = jg + 8 * jj;
            float acc = qkv_b[j];
            DOT32(acc, OFF_WQ + j * 36);
            qv[jj] = acc;
        }
    }
    __syncwarp();
    if (own) {
#pragma unroll
        for (int jj = 0; jj < 4; jj++) sm[OFF_X + hp8 * XS + jg + 8 * jj] = qv[jj];
    }
    __syncthreads();

    {
        const int dh = lane & 15, kvhalf = lane >> 4, hoff = kvhalf << 4;
        for (int c = 0; c < 4; c++) {
            int p = c * 16 + wp;
            int h = p >> 5, q = half * 32 + (p & 31);
            const float* qrow = &sm[OFF_X + q * XS + h * 16];
            float s0 = 0.f, s1 = 0.f;
#pragma unroll
            for (int d2 = 0; d2 < 16; d2++) {
                float qq = qrow[d2];
                s0 = fmaf(qq, sm[OFF_KV + lane * 65 + h * 16 + d2], s0);
                s1 = fmaf(qq, sm[OFF_KV + (lane + 32) * 65 + h * 16 + d2], s1);
            }
            float e0 = expf(s0 * 0.25f), e1 = expf(s1 * 0.25f);
            float inv = 1.f / wredsum(e0 + e1);
            sm[OFF_PROBS + wp * 64 + lane] = e0;
            sm[OFF_PROBS + wp * 64 + 32 + lane] = e1;
            __syncwarp();
            const float* pr = &sm[OFF_PROBS + wp * 64 + (kvhalf ? 32 : 0)];
            const float* vcol = &sm[OFF_KV + (kvhalf ? 32 * 65 : 0) + 32 + h * 16 + dh];
            float acc = 0.f;
#pragma unroll
            for (int k = 0; k < 32; k++) {
                int src = (k + hoff) & 31;
                acc = fmaf(pr[src], vcol[src * 65], acc);
            }
            acc += __shfl_xor_sync(0xffffffffu, acc, 16);
            if (lane < 16) sm[OFF_X + q * XS + h * 16 + lane] = acc * inv;
            __syncwarp();
        }
    }
    __syncthreads();

    LOAD_XR(OFF_X + rowR * XS);
#pragma unroll
    for (int jj = 0; jj < 2; jj++) {
        int j = jgR + 16 * jj;
        float acc = out_b[j];
        DOT32(acc, OFF_WOUT + j * 36);
        sm[OFF_FEAT + rowR * 32 + j] += acc;
    }
    __syncthreads();

#pragma unroll
    for (int rep = 0; rep < 2; rep++) {
        int hp = half * 32 + rep * 16 + wp;
        float v = sm[OFF_FEAT + hp * 32 + lane];
        float mu = wredsum(v) * (1.f / 32.f);
        float df = v - mu;
        float var = wredsum(df * df) * (1.f / 32.f);
        sm[OFF_X + hp * XS + lane] = df * rsqrtf(var + 1e-5f) * ln2_g[lane] + ln2_b[lane];
    }
    __syncthreads();

    LOAD_XR(OFF_X + rowR * XS);
#pragma unroll
    for (int jj = 0; jj < 4; jj++) {
        int f = jgR + 16 * jj;
        float acc = ffn_b1[f];
        DOT32(acc, OFF_WF1 + f * 36);
        sm[OFF_KV + lr * 68 + f] = 0.5f * acc * (1.f + erff(acc * 0.70710678118654752f));
    }
    __syncwarp();

#pragma unroll
    for (int jj = 0; jj < 2; jj++) {
        int d = jgR + 16 * jj;
        float acc = ffn_b2[d];
#pragma unroll
        for (int k8 = 0; k8 < 16; k8++) {
            float4 h4 = *(const float4*)&sm[OFF_KV + lr * 68 + k8 * 4];
            float4 w4 = *(const float4*)&sm[OFF_WF2 + d * 68 + k8 * 4];
            acc = fmaf(w4.x, h4.x, acc);
            acc = fmaf(w4.y, h4.y, acc);
            acc = fmaf(w4.z, h4.z, acc);
            acc = fmaf(w4.w, h4.w, acc);
        }
        g_feat[bidx * 2048 + rowR * 32 + d] = sm[OFF_FEAT + rowR * 32 + d] + acc;
    }
#undef LOAD_XR
#undef DOT32
}

// ============================================================================
// Kernel 3: heads + merge (R9 logic) + PDL: prefetch a/b into registers
// BEFORE waiting on k2 — DRAM streaming overlaps the transformer.
// ============================================================================
__global__ __launch_bounds__(256) void k_merge(
    const float* __restrict__ a, const float* __restrict__ b,
    float* __restrict__ out,
    const float* __restrict__ gate_w, const float* __restrict__ gate_b,
    const float* __restrict__ row_w, const float* __restrict__ row_b,
    const float* __restrict__ col_w, const float* __restrict__ col_b,
    const float* __restrict__ drow_w, const float* __restrict__ drow_b,
    const float* __restrict__ dcol_w, const float* __restrict__ dcol_b,
    const float* __restrict__ delta_scale) {
    const int slice = (NBH - 1) - blockIdx.x;   // reverse: reuse k1's L2 tail
    const int t = threadIdx.x, lane = t & 31, wp = t >> 5;

    __shared__ float s_feat[32];
    __shared__ float s_r[64], s_c[64], s_dr[64], s_dc[64];
    __shared__ float s_gate;

    // prefetch a/b (independent of k2) — issues DRAM traffic immediately
    const float4* a4 = (const float4*)a + slice * 1024;
    const float4* b4 = (const float4*)b + slice * 1024;
    float4 va[4], vb[4];
#pragma unroll
    for (int k = 0; k < 4; k++) { va[k] = a4[t + k * 256]; vb[k] = b4[t + k * 256]; }

    pdl_wait();      // k2's g_feat writes now visible

    if (t < 32) s_feat[t] = g_feat[slice * 32 + t];
    __syncthreads();

    {
        const int mat = wp >> 1;
        const float* w; const float* bb; float* dst;
        if (mat == 0)      { w = row_w;  bb = row_b;  dst = s_r; }
        else if (mat == 1) { w = col_w;  bb = col_b;  dst = s_c; }
        else if (mat == 2) { w = drow_w; bb = drow_b; dst = s_dr; }
        else               { w = dcol_w; bb = dcol_b; dst = s_dc; }
        const int g = lane >> 3;
        const int dsub = lane & 7;
        float4 f4 = ((const float4*)s_feat)[dsub];
        const float dscale = (mat == 2) ? *delta_scale : 1.f;
#pragma unroll
        for (int ii = 0; ii < 8; ii++) {
            int i = (wp & 1) * 32 + ii * 4 + g;
            float4 w4 = ((const float4*)w)[i * 8 + dsub];
            float v = w4.x * f4.x + w4.y * f4.y + w4.z * f4.z + w4.w * f4.w;
            v += __shfl_xor_sync(0xffffffffu, v, 1);
            v += __shfl_xor_sync(0xffffffffu, v, 2);
            v += __shfl_xor_sync(0xffffffffu, v, 4);
            if (dsub == 0) dst[i] = (v + bb[i]) * dscale;
        }
        if (wp == 0) {
            float gv = s_feat[lane] * gate_w[lane];
            gv = wredsum(gv);
            if (lane == 0) s_gate = gv + gate_b[0];
        }
    }
    __syncthreads();

    float4* o4 = (float4*)out + slice * 1024;
    const float gate = s_gate;

#pragma unroll
    for (int k = 0; k < 4; k++) {
        int p = t + k * 256;
        int i = p >> 4;
        float g = gate + s_r[i];
        float dr = s_dr[i];
        float4 c4 = ((const float4*)s_c)[p & 15];
        float4 dc4 = ((const float4*)s_dc)[p & 15];
        float4 r;
        { float m = fsig(g + c4.x); r.x = vb[k].x + m * (va[k].x - vb[k].x) + dr * dc4.x; }
        { float m = fsig(g + c4.y); r.y = vb[k].y + m * (va[k].y - vb[k].y) + dr * dc4.y; }
        { float m = fsig(g + c4.z); r.z = vb[k].z + m * (va[k].z - vb[k].z) + dr * dc4.z; }
        { float m = fsig(g + c4.w); r.w = vb[k].w + m * (va[k].w - vb[k].w) + dr * dc4.w; }
        __stcs(&o4[p], r);   // streaming store: don't pollute L2
    }
}

// ============================================================================
extern "C" void kernel_launch(void* const* d_in, const int* in_sizes, int n_in,
                              void* d_out, int out_size) {
    const float* a = (const float*)d_in[0];
    const float* b = (const float*)d_in[1];

    const int smem_bytes = SM_FLOATS * 4;
    cudaFuncSetAttribute(k_transformer, cudaFuncAttributeMaxDynamicSharedMemorySize,
                         smem_bytes);

    k_stats<<<NBH, 256>>>(a, b);

    // k2: PDL-dependent on k1
    {
        cudaLaunchConfig_t cfg = {};
        cfg.gridDim = dim3(128, 1, 1);
        cfg.blockDim = dim3(512, 1, 1);
        cfg.dynamicSmemBytes = smem_bytes;
        cudaLaunchAttribute attr[1];
        attr[0].id = cudaLaunchAttributeProgrammaticStreamSerialization;
        attr[0].val.programmaticStreamSerializationAllowed = 1;
        cfg.attrs = attr;
        cfg.numAttrs = 1;
        cudaLaunchKernelEx(&cfg, k_transformer,
            (const float*)d_in[2],
            (const float*)d_in[3], (const float*)d_in[4],
            (const float*)d_in[5], (const float*)d_in[6],
            (const float*)d_in[7], (const float*)d_in[8],
            (const float*)d_in[9], (const float*)d_in[10],
            (const float*)d_in[11], (const float*)d_in[12],
            (const float*)d_in[13], (const float*)d_in[14],
            (const float*)d_in[15], (const float*)d_in[16]);
    }

    // k3: PDL-dependent on k2 (prefetches a/b before waiting)
    {
        cudaLaunchConfig_t cfg = {};
        cfg.gridDim = dim3(NBH, 1, 1);
        cfg.blockDim = dim3(256, 1, 1);
        cfg.dynamicSmemBytes = 0;
        cudaLaunchAttribute attr[1];
        attr[0].id = cudaLaunchAttributeProgrammaticStreamSerialization;
        attr[0].val.programmaticStreamSerializationAllowed = 1;
        cfg.attrs = attr;
        cfg.numAttrs = 1;
        cudaLaunchKernelEx(&cfg, k_merge,
            a, b, (float*)d_out,
            (const float*)d_in[17], (const float*)d_in[18],
            (const float*)d_in[19], (const float*)d_in[20],
            (const float*)d_in[21], (const float*)d_in[22],
            (const float*)d_in[23], (const float*)d_in[24],
            (const float*)d_in[25], (const float*)d_in[26],
            (const float*)d_in[27]);
    }
}